// round 1
// baseline (speedup 1.0000x reference)
#include <cuda_runtime.h>
#include <math.h>

#define BB 2048
#define KK 256
#define AD 512
#define IN 768
#define NUM_E 100000
#define NUM_R 500

// scratch (device-global: no allocations allowed)
__device__ float g_X [BB * AD];
__device__ float g_X2[BB * AD];
__device__ float g_P [BB * NUM_R];

// ---------------------------------------------------------------------------
// GEMM1: X = relu(cat(E,H,Q) @ W1^T + b1)   [2048,768]x[512,768]^T -> [2048,512]
// 64x64 tile, 256 threads, 4x4 microtile.
// ---------------------------------------------------------------------------
__global__ __launch_bounds__(256) void gemm1_concat(
    const float* __restrict__ E, const float* __restrict__ H,
    const float* __restrict__ Qp, const float* __restrict__ W1,
    const float* __restrict__ b1, float* __restrict__ C)
{
    __shared__ float As[16][65];
    __shared__ float Bs[16][65];
    const int m0 = blockIdx.x * 64;
    const int n0 = blockIdx.y * 64;
    const int t  = threadIdx.x;
    const int row = t >> 2;
    const int kq  = (t & 3) << 2;
    const int tx = t & 15, ty = t >> 4;
    float acc[4][4] = {};

    for (int k0 = 0; k0 < IN; k0 += 16) {
        const int c = k0 + kq;
        const float* src = (c < 256) ? (E  + (m0 + row) * 256 + c)
                         : (c < 512) ? (H  + (m0 + row) * 256 + (c - 256))
                                     : (Qp + (m0 + row) * 256 + (c - 512));
        float4 av = *(const float4*)src;
        As[kq + 0][row] = av.x; As[kq + 1][row] = av.y;
        As[kq + 2][row] = av.z; As[kq + 3][row] = av.w;
        float4 wv = *(const float4*)&W1[(n0 + row) * IN + c];
        Bs[kq + 0][row] = wv.x; Bs[kq + 1][row] = wv.y;
        Bs[kq + 2][row] = wv.z; Bs[kq + 3][row] = wv.w;
        __syncthreads();
#pragma unroll
        for (int kk = 0; kk < 16; kk++) {
            float a0 = As[kk][ty * 4 + 0], a1 = As[kk][ty * 4 + 1];
            float a2 = As[kk][ty * 4 + 2], a3 = As[kk][ty * 4 + 3];
            float w0 = Bs[kk][tx * 4 + 0], w1 = Bs[kk][tx * 4 + 1];
            float w2 = Bs[kk][tx * 4 + 2], w3 = Bs[kk][tx * 4 + 3];
            acc[0][0] += a0 * w0; acc[0][1] += a0 * w1; acc[0][2] += a0 * w2; acc[0][3] += a0 * w3;
            acc[1][0] += a1 * w0; acc[1][1] += a1 * w1; acc[1][2] += a1 * w2; acc[1][3] += a1 * w3;
            acc[2][0] += a2 * w0; acc[2][1] += a2 * w1; acc[2][2] += a2 * w2; acc[2][3] += a2 * w3;
            acc[3][0] += a3 * w0; acc[3][1] += a3 * w1; acc[3][2] += a3 * w2; acc[3][3] += a3 * w3;
        }
        __syncthreads();
    }
#pragma unroll
    for (int i = 0; i < 4; i++) {
        const int m = m0 + ty * 4 + i;
#pragma unroll
        for (int j = 0; j < 4; j++) {
            const int n = n0 + tx * 4 + j;
            float v = acc[i][j] + b1[n];
            C[m * AD + n] = fmaxf(v, 0.0f);
        }
    }
}

// ---------------------------------------------------------------------------
// Generic SGEMM  C[M,N] = A[M,Kt](lda) @ Wm[N,Kt](ldw)^T + bias
// M multiple of 64; N guarded. 64x64 tile, 256 threads, 4x4 microtile.
// ---------------------------------------------------------------------------
__global__ __launch_bounds__(256) void sgemm_nt(
    const float* __restrict__ A, int lda,
    const float* __restrict__ Wm, int ldw,
    const float* __restrict__ bias,
    float* __restrict__ C, int ldc, int N, int Kt)
{
    __shared__ float As[16][65];
    __shared__ float Bs[16][65];
    const int m0 = blockIdx.x * 64;
    const int n0 = blockIdx.y * 64;
    const int t  = threadIdx.x;
    const int row = t >> 2;
    const int kq  = (t & 3) << 2;
    const int tx = t & 15, ty = t >> 4;
    float acc[4][4] = {};

    for (int k0 = 0; k0 < Kt; k0 += 16) {
        float4 av = *(const float4*)&A[(m0 + row) * lda + k0 + kq];
        As[kq + 0][row] = av.x; As[kq + 1][row] = av.y;
        As[kq + 2][row] = av.z; As[kq + 3][row] = av.w;
        const int wn = n0 + row;
        float4 wv = make_float4(0.f, 0.f, 0.f, 0.f);
        if (wn < N) wv = *(const float4*)&Wm[wn * ldw + k0 + kq];
        Bs[kq + 0][row] = wv.x; Bs[kq + 1][row] = wv.y;
        Bs[kq + 2][row] = wv.z; Bs[kq + 3][row] = wv.w;
        __syncthreads();
#pragma unroll
        for (int kk = 0; kk < 16; kk++) {
            float a0 = As[kk][ty * 4 + 0], a1 = As[kk][ty * 4 + 1];
            float a2 = As[kk][ty * 4 + 2], a3 = As[kk][ty * 4 + 3];
            float w0 = Bs[kk][tx * 4 + 0], w1 = Bs[kk][tx * 4 + 1];
            float w2 = Bs[kk][tx * 4 + 2], w3 = Bs[kk][tx * 4 + 3];
            acc[0][0] += a0 * w0; acc[0][1] += a0 * w1; acc[0][2] += a0 * w2; acc[0][3] += a0 * w3;
            acc[1][0] += a1 * w0; acc[1][1] += a1 * w1; acc[1][2] += a1 * w2; acc[1][3] += a1 * w3;
            acc[2][0] += a2 * w0; acc[2][1] += a2 * w1; acc[2][2] += a2 * w2; acc[2][3] += a2 * w3;
            acc[3][0] += a3 * w0; acc[3][1] += a3 * w1; acc[3][2] += a3 * w2; acc[3][3] += a3 * w3;
        }
        __syncthreads();
    }
#pragma unroll
    for (int i = 0; i < 4; i++) {
        const int m = m0 + ty * 4 + i;
#pragma unroll
        for (int j = 0; j < 4; j++) {
            const int n = n0 + tx * 4 + j;
            if (n < N) {
                float v = acc[i][j];
                if (bias) v += bias[n];
                C[m * ldc + n] = v;
            }
        }
    }
}

// ---------------------------------------------------------------------------
// Per-row: scores = P[b, r_space] + <emb_e[e_space], X2_e[b]> - (1-mask)*HUGE
// then masked softmax + entropy. One block (256 threads) per batch row.
// ---------------------------------------------------------------------------
__global__ __launch_bounds__(256) void score_softmax(
    const float* __restrict__ X2, const float* __restrict__ P,
    const float* __restrict__ emb_e, const float* __restrict__ mask,
    const int* __restrict__ r_space, const int* __restrict__ e_space,
    float* __restrict__ out_dist, float* __restrict__ out_ent, int write_ent)
{
    const int b = blockIdx.x;
    __shared__ float x2e[256];
    __shared__ float sc[KK];
    __shared__ float red1[8], red2[8], red3[8];
    const int t = threadIdx.x;
    const int warp = t >> 5, lane = t & 31;

    x2e[t] = X2[b * AD + 256 + t];
    __syncthreads();

    const float4 xa = *(const float4*)&x2e[lane * 4];
    const float4 xb = *(const float4*)&x2e[lane * 4 + 128];

    // each warp: 32 k's, one 256-float dot per k (coalesced 1KB row from L2)
    for (int i = 0; i < 32; i++) {
        const int k = warp * 32 + i;
        const int e = e_space[b * KK + k];
        const float4* er = (const float4*)(emb_e + (size_t)e * 256);
        const float4 v0 = er[lane];
        const float4 v1 = er[lane + 32];
        float s = v0.x * xa.x + v0.y * xa.y + v0.z * xa.z + v0.w * xa.w
                + v1.x * xb.x + v1.y * xb.y + v1.z * xb.z + v1.w * xb.w;
#pragma unroll
        for (int o = 16; o; o >>= 1) s += __shfl_xor_sync(0xFFFFFFFFu, s, o);
        if (lane == 0) sc[k] = s;
    }
    __syncthreads();

    const int r = r_space[b * KK + t];
    float s = sc[t] + P[b * NUM_R + r] - (1.0f - mask[b * KK + t]) * 1e31f;

    // block max
    float m = s;
#pragma unroll
    for (int o = 16; o; o >>= 1) m = fmaxf(m, __shfl_xor_sync(0xFFFFFFFFu, m, o));
    if (lane == 0) red1[warp] = m;
    __syncthreads();
    float bm = red1[0];
#pragma unroll
    for (int w = 1; w < 8; w++) bm = fmaxf(bm, red1[w]);

    const float p = expf(s - bm);
    float sum = p;
#pragma unroll
    for (int o = 16; o; o >>= 1) sum += __shfl_xor_sync(0xFFFFFFFFu, sum, o);
    if (lane == 0) red2[warp] = sum;
    __syncthreads();
    float bs = 0.f;
#pragma unroll
    for (int w = 0; w < 8; w++) bs += red2[w];

    const float dist = p / bs;
    out_dist[b * KK + t] = dist;

    float es = -dist * logf(dist + 1e-20f);
#pragma unroll
    for (int o = 16; o; o >>= 1) es += __shfl_xor_sync(0xFFFFFFFFu, es, o);
    if (lane == 0) red3[warp] = es;
    __syncthreads();
    if (t == 0 && write_ent) {
        float tot = 0.f;
#pragma unroll
        for (int w = 0; w < 8; w++) tot += red3[w];
        out_ent[b] = tot;
    }
}

extern "C" void kernel_launch(void* const* d_in, const int* in_sizes, int n_in,
                              void* d_out, int out_size)
{
    const float* E     = (const float*)d_in[0];
    const float* H     = (const float*)d_in[1];
    const float* Q     = (const float*)d_in[2];
    const float* W1    = (const float*)d_in[3];
    const float* b1    = (const float*)d_in[4];
    const float* W2    = (const float*)d_in[5];
    const float* b2    = (const float*)d_in[6];
    const float* emb_r = (const float*)d_in[7];
    const float* emb_e = (const float*)d_in[8];
    const float* mask  = (const float*)d_in[9];
    const int*   r_sp  = (const int*)d_in[10];
    const int*   e_sp  = (const int*)d_in[11];
    float* out = (float*)d_out;

    float *gX, *gX2, *gP;
    cudaGetSymbolAddress((void**)&gX,  g_X);
    cudaGetSymbolAddress((void**)&gX2, g_X2);
    cudaGetSymbolAddress((void**)&gP,  g_P);

    const int write_ent = (out_size >= BB * KK + BB) ? 1 : 0;

    gemm1_concat<<<dim3(BB / 64, AD / 64), 256>>>(E, H, Q, W1, b1, gX);
    sgemm_nt<<<dim3(BB / 64, AD / 64), 256>>>(gX, AD, W2, AD, b2, gX2, AD, AD, AD);
    sgemm_nt<<<dim3(BB / 64, (NUM_R + 63) / 64), 256>>>(gX2, AD, emb_r, 256, nullptr,
                                                        gP, NUM_R, NUM_R, 256);
    score_softmax<<<BB, 256>>>(gX2, gP, emb_e, mask, r_sp, e_sp,
                               out, out + (size_t)BB * KK, write_ent);
}

// round 3
// speedup vs baseline: 1.3002x; 1.3002x over previous
#include <cuda_runtime.h>
#include <cuda_bf16.h>
#include <math.h>
#include <stdint.h>

#define BB 2048
#define KK 256
#define AD 512
#define IN 768

// GEMM tiling
#define TM 64
#define TN 128
#define TKC 64                 // K-chunk
#define PAD_LD 72              // padded smem row (bf16 elems): 144B stride, conflict-free
#define A_ST_EL (TM * PAD_LD)  // 4608
#define B_ST_EL (TN * PAD_LD)  // 9216
#define GEMM_SMEM ((2 * A_ST_EL + 2 * B_ST_EL) * 2)   // 55296 B

// ---------------- scratch (device globals: no allocs allowed) ----------------
__device__ __nv_bfloat16 g_A1 [(size_t)BB * 2304];   // split concat(E,H,Q)  [hi|lo|hi]
__device__ __nv_bfloat16 g_W1s[(size_t)AD * 2304];   // split W1             [hi|hi|lo]
__device__ __nv_bfloat16 g_A2 [(size_t)BB * 1536];   // split X (G1 out)
__device__ __nv_bfloat16 g_W2s[(size_t)AD * 1536];
__device__ __nv_bfloat16 g_A3 [(size_t)BB * 768];    // split X2[:, :256]
__device__ __nv_bfloat16 g_Ers[(size_t)512 * 768];   // split emb_r (rows 500..511 zero)
__device__ float g_X2e[(size_t)BB * 256];            // X2[:, 256:512] fp32
__device__ float g_P  [(size_t)BB * 512];            // X2[:, :256] @ emb_r^T

// ---------------- helpers ----------------
__device__ __forceinline__ uint32_t smem_u32(const void* p) {
    uint32_t a;
    asm("{ .reg .u64 t; cvta.to.shared.u64 t, %1; cvt.u32.u64 %0, t; }" : "=r"(a) : "l"(p));
    return a;
}
#define CP_ASYNC16(dst, src) \
    asm volatile("cp.async.cg.shared.global [%0], [%1], 16;" :: "r"(dst), "l"(src) : "memory")
#define CP_COMMIT()  asm volatile("cp.async.commit_group;" ::: "memory")

__device__ __forceinline__ void ldsm_x4(uint32_t* r, uint32_t addr) {
    asm volatile("ldmatrix.sync.aligned.m8n8.x4.shared.b16 {%0,%1,%2,%3}, [%4];"
                 : "=r"(r[0]), "=r"(r[1]), "=r"(r[2]), "=r"(r[3]) : "r"(addr));
}
__device__ __forceinline__ void mma16816(float* c, const uint32_t* a, const uint32_t* b) {
    asm volatile(
        "mma.sync.aligned.m16n8k16.row.col.f32.bf16.bf16.f32 "
        "{%0,%1,%2,%3}, {%4,%5,%6,%7}, {%8,%9}, {%0,%1,%2,%3};"
        : "+f"(c[0]), "+f"(c[1]), "+f"(c[2]), "+f"(c[3])
        : "r"(a[0]), "r"(a[1]), "r"(a[2]), "r"(a[3]), "r"(b[0]), "r"(b[1]));
}

// ---------------- conversion kernels ----------------
// A-side split: [hi | lo | hi]
__global__ __launch_bounds__(256) void conv_A1(
    const float* __restrict__ E, const float* __restrict__ H, const float* __restrict__ Q,
    __nv_bfloat16* __restrict__ out)
{
    int idx = blockIdx.x * 256 + threadIdx.x;        // over BB*IN
    int m = idx / IN, c = idx % IN;
    float v = (c < 256) ? E[m * 256 + c] : (c < 512) ? H[m * 256 + (c - 256)] : Q[m * 256 + (c - 512)];
    __nv_bfloat16 h = __float2bfloat16_rn(v);
    __nv_bfloat16 l = __float2bfloat16_rn(v - __bfloat162float(h));
    size_t r = (size_t)m * 2304;
    out[r + c] = h; out[r + 768 + c] = l; out[r + 1536 + c] = h;
}

// B-side split: [hi | hi | lo]; rows >= Nvalid zero-padded
__global__ __launch_bounds__(256) void conv_B(
    const float* __restrict__ W, __nv_bfloat16* __restrict__ out, int Kc, int Nvalid)
{
    int idx = blockIdx.x * 256 + threadIdx.x;        // over 512*Kc
    int n = idx / Kc, k = idx % Kc;
    float v = (n < Nvalid) ? W[(size_t)n * Kc + k] : 0.0f;
    __nv_bfloat16 h = __float2bfloat16_rn(v);
    __nv_bfloat16 l = __float2bfloat16_rn(v - __bfloat162float(h));
    size_t r = (size_t)n * 3 * Kc;
    out[r + k] = h; out[r + Kc + k] = h; out[r + 2 * Kc + k] = l;
}

// ---------------- HMMA GEMM ----------------
// C[2048, 512] = A'[2048, K'] @ B'[512, K']^T   (bf16 split operands, fp32 accum)
// MODE 0: +b1, relu, split-store into g_A2 (W=512)
// MODE 1: +b2; cols<256 -> split into g_A3 (W=256); cols>=256 -> fp32 g_X2e
// MODE 2: fp32 -> g_P (stride 512)
template <int MODE>
__global__ __launch_bounds__(256) void gemm_mma(
    const __nv_bfloat16* __restrict__ A, const __nv_bfloat16* __restrict__ Bm,
    int ldk, int nchunks, const float* __restrict__ bias,
    __nv_bfloat16* __restrict__ outs, float* __restrict__ outf)
{
    extern __shared__ __nv_bfloat16 sm[];
    const uint32_t smA = smem_u32(sm);                       // bytes
    const uint32_t smB = smA + 2 * A_ST_EL * 2;

    const int t = threadIdx.x;
    const int warp = t >> 5, lane = t & 31;
    const int m0 = blockIdx.x * TM;
    const int n0 = blockIdx.y * TN;
    const int wm = (warp >> 2) * 32;       // 0 or 32
    const int wn = (warp & 3) * 32;        // 0..96

    // ldmatrix lane address components
    const int rA  = lane & 15;             // A: lanes 0-15 rows, 16-31 repeat
    const int cA8 = (lane >> 4) * 8;       //    col +8 for upper half
    const int rB  = (lane & 7) + ((lane >> 4) & 1) * 8;
    const int cB8 = ((lane >> 3) & 1) * 8;

    float acc[2][4][4] = {};

    // cp.async loaders: 16B segments
    auto load_stage = [&](int s, int chunk) {
        const size_t k0 = (size_t)chunk * TKC;
        const uint32_t dA = smA + s * A_ST_EL * 2;
        const uint32_t dB = smB + s * B_ST_EL * 2;
        // A: 64 rows x 64 cols = 512 segs; 2 per thread
        #pragma unroll
        for (int i = 0; i < 2; i++) {
            int v = t + i * 256;
            int row = v >> 3, seg = v & 7;
            CP_ASYNC16(dA + (row * PAD_LD + seg * 8) * 2,
                       A + (size_t)(m0 + row) * ldk + k0 + seg * 8);
        }
        // B: 128 rows x 64 cols = 1024 segs; 4 per thread
        #pragma unroll
        for (int i = 0; i < 4; i++) {
            int v = t + i * 256;
            int row = v >> 3, seg = v & 7;
            CP_ASYNC16(dB + (row * PAD_LD + seg * 8) * 2,
                       Bm + (size_t)(n0 + row) * ldk + k0 + seg * 8);
        }
        CP_COMMIT();
    };

    load_stage(0, 0);

    for (int i = 0; i < nchunks; i++) {
        if (i + 1 < nchunks) {
            load_stage((i + 1) & 1, i + 1);
            asm volatile("cp.async.wait_group 1;" ::: "memory");
        } else {
            asm volatile("cp.async.wait_group 0;" ::: "memory");
        }
        __syncthreads();

        const uint32_t sAst = smA + (i & 1) * A_ST_EL * 2;
        const uint32_t sBst = smB + (i & 1) * B_ST_EL * 2;
        #pragma unroll
        for (int ks = 0; ks < 4; ks++) {
            const int k0 = ks * 16;
            uint32_t a0[4], a1[4], b0[4], b1[4];
            ldsm_x4(a0, sAst + ((wm +      rA) * PAD_LD + k0 + cA8) * 2);
            ldsm_x4(a1, sAst + ((wm + 16 + rA) * PAD_LD + k0 + cA8) * 2);
            ldsm_x4(b0, sBst + ((wn +      rB) * PAD_LD + k0 + cB8) * 2);
            ldsm_x4(b1, sBst + ((wn + 16 + rB) * PAD_LD + k0 + cB8) * 2);
            #pragma unroll
            for (int mi = 0; mi < 2; mi++) {
                const uint32_t* aa = mi ? a1 : a0;
                mma16816(acc[mi][0], aa, b0 + 0);
                mma16816(acc[mi][1], aa, b0 + 2);
                mma16816(acc[mi][2], aa, b1 + 0);
                mma16816(acc[mi][3], aa, b1 + 2);
            }
        }
        __syncthreads();
    }

    // ---------------- epilogue ----------------
    #pragma unroll
    for (int mi = 0; mi < 2; mi++) {
        #pragma unroll
        for (int h = 0; h < 2; h++) {
            const int row = m0 + wm + 16 * mi + 8 * h + (lane >> 2);
            #pragma unroll
            for (int j = 0; j < 4; j++) {
                const int col = n0 + wn + 8 * j + 2 * (lane & 3);
                float v0 = acc[mi][j][2 * h];
                float v1 = acc[mi][j][2 * h + 1];
                if (MODE == 2) {
                    *(float2*)(outf + (size_t)row * 512 + col) = make_float2(v0, v1);
                } else {
                    v0 += __ldg(&bias[col]);
                    v1 += __ldg(&bias[col + 1]);
                    if (MODE == 0) { v0 = fmaxf(v0, 0.0f); v1 = fmaxf(v1, 0.0f); }
                    if (MODE == 1 && col >= 256) {
                        *(float2*)(outf + (size_t)row * 256 + (col - 256)) = make_float2(v0, v1);
                    } else {
                        const int W = (MODE == 0) ? 512 : 256;
                        __nv_bfloat16 h0 = __float2bfloat16_rn(v0);
                        __nv_bfloat16 h1 = __float2bfloat16_rn(v1);
                        __nv_bfloat16 l0 = __float2bfloat16_rn(v0 - __bfloat162float(h0));
                        __nv_bfloat16 l1 = __float2bfloat16_rn(v1 - __bfloat162float(h1));
                        __nv_bfloat162 hh; hh.x = h0; hh.y = h1;
                        __nv_bfloat162 ll; ll.x = l0; ll.y = l1;
                        __nv_bfloat16* r0 = outs + (size_t)row * (3 * W) + col;
                        *(__nv_bfloat162*)(r0)         = hh;
                        *(__nv_bfloat162*)(r0 + W)     = ll;
                        *(__nv_bfloat162*)(r0 + 2 * W) = hh;
                    }
                }
            }
        }
    }
}

// ---------------- score + softmax + entropy ----------------
__global__ __launch_bounds__(256) void score_softmax(
    const float* __restrict__ X2e, const float* __restrict__ P,
    const float* __restrict__ emb_e, const float* __restrict__ mask,
    const int* __restrict__ r_space, const int* __restrict__ e_space,
    float* __restrict__ out_dist, float* __restrict__ out_ent, int write_ent)
{
    const int b = blockIdx.x;
    __shared__ float x2e[256];
    __shared__ float sc[KK];
    __shared__ float red1[8], red2[8], red3[8];
    const int t = threadIdx.x;
    const int warp = t >> 5, lane = t & 31;

    x2e[t] = X2e[b * 256 + t];
    __syncthreads();

    const float4 xa = *(const float4*)&x2e[lane * 4];
    const float4 xb = *(const float4*)&x2e[lane * 4 + 128];

    for (int i = 0; i < 32; i++) {
        const int k = warp * 32 + i;
        const int e = e_space[b * KK + k];
        const float4* er = (const float4*)(emb_e + (size_t)e * 256);
        const float4 v0 = er[lane];
        const float4 v1 = er[lane + 32];
        float s = v0.x * xa.x + v0.y * xa.y + v0.z * xa.z + v0.w * xa.w
                + v1.x * xb.x + v1.y * xb.y + v1.z * xb.z + v1.w * xb.w;
#pragma unroll
        for (int o = 16; o; o >>= 1) s += __shfl_xor_sync(0xFFFFFFFFu, s, o);
        if (lane == 0) sc[k] = s;
    }
    __syncthreads();

    const int r = r_space[b * KK + t];
    float s = sc[t] + P[b * 512 + r] - (1.0f - mask[b * KK + t]) * 1e31f;

    float mx = s;
#pragma unroll
    for (int o = 16; o; o >>= 1) mx = fmaxf(mx, __shfl_xor_sync(0xFFFFFFFFu, mx, o));
    if (lane == 0) red1[warp] = mx;
    __syncthreads();
    float bm = red1[0];
#pragma unroll
    for (int w = 1; w < 8; w++) bm = fmaxf(bm, red1[w]);

    const float p = expf(s - bm);
    float sum = p;
#pragma unroll
    for (int o = 16; o; o >>= 1) sum += __shfl_xor_sync(0xFFFFFFFFu, sum, o);
    if (lane == 0) red2[warp] = sum;
    __syncthreads();
    float bs = 0.f;
#pragma unroll
    for (int w = 0; w < 8; w++) bs += red2[w];

    const float dist = p / bs;
    out_dist[b * KK + t] = dist;

    float es = -dist * logf(dist + 1e-20f);
#pragma unroll
    for (int o = 16; o; o >>= 1) es += __shfl_xor_sync(0xFFFFFFFFu, es, o);
    if (lane == 0) red3[warp] = es;
    __syncthreads();
    if (t == 0 && write_ent) {
        float tot = 0.f;
#pragma unroll
        for (int w = 0; w < 8; w++) tot += red3[w];
        out_ent[b] = tot;
    }
}

// ---------------- launcher ----------------
extern "C" void kernel_launch(void* const* d_in, const int* in_sizes, int n_in,
                              void* d_out, int out_size)
{
    const float* E     = (const float*)d_in[0];
    const float* H     = (const float*)d_in[1];
    const float* Q     = (const float*)d_in[2];
    const float* W1    = (const float*)d_in[3];
    const float* b1    = (const float*)d_in[4];
    const float* W2    = (const float*)d_in[5];
    const float* b2    = (const float*)d_in[6];
    const float* emb_r = (const float*)d_in[7];
    const float* emb_e = (const float*)d_in[8];
    const float* mask  = (const float*)d_in[9];
    const int*   r_sp  = (const int*)d_in[10];
    const int*   e_sp  = (const int*)d_in[11];
    float* out = (float*)d_out;

    __nv_bfloat16 *gA1, *gW1s, *gA2, *gW2s, *gA3, *gErs;
    float *gX2e, *gP;
    cudaGetSymbolAddress((void**)&gA1,  g_A1);
    cudaGetSymbolAddress((void**)&gW1s, g_W1s);
    cudaGetSymbolAddress((void**)&gA2,  g_A2);
    cudaGetSymbolAddress((void**)&gW2s, g_W2s);
    cudaGetSymbolAddress((void**)&gA3,  g_A3);
    cudaGetSymbolAddress((void**)&gErs, g_Ers);
    cudaGetSymbolAddress((void**)&gX2e, g_X2e);
    cudaGetSymbolAddress((void**)&gP,   g_P);

    cudaFuncSetAttribute(gemm_mma<0>, cudaFuncAttributeMaxDynamicSharedMemorySize, GEMM_SMEM);
    cudaFuncSetAttribute(gemm_mma<1>, cudaFuncAttributeMaxDynamicSharedMemorySize, GEMM_SMEM);
    cudaFuncSetAttribute(gemm_mma<2>, cudaFuncAttributeMaxDynamicSharedMemorySize, GEMM_SMEM);

    const int write_ent = (out_size >= BB * KK + BB) ? 1 : 0;

    conv_A1<<<(BB * IN) / 256, 256>>>(E, H, Q, gA1);
    conv_B<<<(512 * 768) / 256, 256>>>(W1, gW1s, 768, 512);
    conv_B<<<(512 * 512) / 256, 256>>>(W2, gW2s, 512, 512);
    conv_B<<<(512 * 256) / 256, 256>>>(emb_r, gErs, 256, 500);

    gemm_mma<0><<<dim3(BB / TM, 4), 256, GEMM_SMEM>>>(gA1, gW1s, 2304, 36, b1, gA2, nullptr);
    gemm_mma<1><<<dim3(BB / TM, 4), 256, GEMM_SMEM>>>(gA2, gW2s, 1536, 24, b2, gA3, gX2e);
    gemm_mma<2><<<dim3(BB / TM, 4), 256, GEMM_SMEM>>>(gA3, gErs,  768, 12, nullptr, nullptr, gP);

    score_softmax<<<BB, 256>>>(gX2e, gP, emb_e, mask, r_sp, e_sp,
                               out, out + (size_t)BB * KK, write_ent);
}

// round 4
// speedup vs baseline: 1.7388x; 1.3374x over previous
#include <cuda_runtime.h>
#include <cuda_bf16.h>
#include <math.h>
#include <stdint.h>

#define BB 2048
#define KK 256
#define AD 512
#define IN 768

// GEMM tiling
#define TM 64
#define TN 128
#define TKC 64                 // K-chunk (bf16 elems)
#define PAD_LD 72              // padded smem row (bf16): 144B stride, conflict-free ldmatrix
#define A_ST_EL (TM * PAD_LD)  // 4608
#define B_ST_EL (TN * PAD_LD)  // 9216
#define NSTAGE 3
#define GEMM_SMEM (NSTAGE * (A_ST_EL + B_ST_EL) * 2)   // 82944 B

// ---------------- scratch (device globals: no allocs allowed) ----------------
__device__ __nv_bfloat16 g_A1 [(size_t)BB * 2304];   // split concat(E,H,Q)  [hi|lo|hi]
__device__ __nv_bfloat16 g_W1s[(size_t)AD * 2304];   // split W1             [hi|hi|lo]
__device__ __nv_bfloat16 g_A2 [(size_t)BB * 1536];   // split X (G1 out)
__device__ __nv_bfloat16 g_W2s[(size_t)AD * 1536];
__device__ __nv_bfloat16 g_A3 [(size_t)BB * 768];    // split X2[:, :256]
__device__ __nv_bfloat16 g_Ers[(size_t)512 * 768];   // split emb_r (rows 500..511 zero)
__device__ float g_X2e[(size_t)BB * 256];            // X2[:, 256:512] fp32
__device__ float g_P  [(size_t)BB * 512];            // X2[:, :256] @ emb_r^T

// ---------------- helpers ----------------
__device__ __forceinline__ uint32_t smem_u32(const void* p) {
    uint32_t a;
    asm("{ .reg .u64 t; cvta.to.shared.u64 t, %1; cvt.u32.u64 %0, t; }" : "=r"(a) : "l"(p));
    return a;
}
#define CP_ASYNC16(dst, src) \
    asm volatile("cp.async.cg.shared.global [%0], [%1], 16;" :: "r"(dst), "l"(src) : "memory")
#define CP_COMMIT()  asm volatile("cp.async.commit_group;" ::: "memory")
#define CP_WAIT(n)   asm volatile("cp.async.wait_group %0;" :: "n"(n) : "memory")

__device__ __forceinline__ void ldsm_x4(uint32_t* r, uint32_t addr) {
    asm volatile("ldmatrix.sync.aligned.m8n8.x4.shared.b16 {%0,%1,%2,%3}, [%4];"
                 : "=r"(r[0]), "=r"(r[1]), "=r"(r[2]), "=r"(r[3]) : "r"(addr));
}
__device__ __forceinline__ void mma16816(float* c, const uint32_t* a, const uint32_t* b) {
    asm volatile(
        "mma.sync.aligned.m16n8k16.row.col.f32.bf16.bf16.f32 "
        "{%0,%1,%2,%3}, {%4,%5,%6,%7}, {%8,%9}, {%0,%1,%2,%3};"
        : "+f"(c[0]), "+f"(c[1]), "+f"(c[2]), "+f"(c[3])
        : "r"(a[0]), "r"(a[1]), "r"(a[2]), "r"(a[3]), "r"(b[0]), "r"(b[1]));
}

// split a float4 into hi/lo bf16 quads and store 8B each
__device__ __forceinline__ void split_store4(float4 v, __nv_bfloat16* d_hi,
                                             __nv_bfloat16* d_lo, __nv_bfloat16* d_hi2)
{
    __align__(8) __nv_bfloat16 hh[4], ll[4];
    hh[0] = __float2bfloat16_rn(v.x); ll[0] = __float2bfloat16_rn(v.x - __bfloat162float(hh[0]));
    hh[1] = __float2bfloat16_rn(v.y); ll[1] = __float2bfloat16_rn(v.y - __bfloat162float(hh[1]));
    hh[2] = __float2bfloat16_rn(v.z); ll[2] = __float2bfloat16_rn(v.z - __bfloat162float(hh[2]));
    hh[3] = __float2bfloat16_rn(v.w); ll[3] = __float2bfloat16_rn(v.w - __bfloat162float(hh[3]));
    *(uint2*)d_hi  = *(uint2*)hh;
    *(uint2*)d_lo  = *(uint2*)ll;
    *(uint2*)d_hi2 = *(uint2*)hh;
}

// ---------------- fused conversion kernel ----------------
// quad-indexed over 4 regions:
//  R0: A1  (BB x 768)  -> [hi|lo|hi], src concat(E,H,Q)
//  R1: W1s (512 x 768) -> [hi|hi|lo]
//  R2: W2s (512 x 512) -> [hi|hi|lo]
//  R3: Ers (512 x 256) -> [hi|hi|lo], rows >= 500 zero
#define Q_R0 (BB * IN / 4)               // 393216
#define Q_R1 (Q_R0 + 512 * 768 / 4)      // 491520
#define Q_R2 (Q_R1 + 512 * 512 / 4)      // 557056
#define Q_TOT (Q_R2 + 512 * 256 / 4)     // 589824

__global__ __launch_bounds__(256) void conv_all(
    const float* __restrict__ E, const float* __restrict__ H, const float* __restrict__ Qm,
    const float* __restrict__ W1, const float* __restrict__ W2, const float* __restrict__ emb_r,
    __nv_bfloat16* __restrict__ A1, __nv_bfloat16* __restrict__ W1s,
    __nv_bfloat16* __restrict__ W2s, __nv_bfloat16* __restrict__ Ers)
{
    const int q = blockIdx.x * 256 + threadIdx.x;
    if (q < Q_R0) {
        const int m = q / 192, c = (q % 192) * 4;
        const float* src = (c < 256) ? (E + m * 256 + c)
                         : (c < 512) ? (H + m * 256 + (c - 256))
                                     : (Qm + m * 256 + (c - 512));
        float4 v = *(const float4*)src;
        __nv_bfloat16* r = A1 + (size_t)m * 2304 + c;
        split_store4(v, r, r + 768, r + 1536);          // [hi|lo|hi]
    } else if (q < Q_R1) {
        const int q2 = q - Q_R0;
        const int n = q2 / 192, k = (q2 % 192) * 4;
        float4 v = *(const float4*)(W1 + (size_t)n * 768 + k);
        __nv_bfloat16* r = W1s + (size_t)n * 2304 + k;
        split_store4(v, r, r + 2 * 768, r + 768);       // [hi|hi|lo]
    } else if (q < Q_R2) {
        const int q2 = q - Q_R1;
        const int n = q2 / 128, k = (q2 % 128) * 4;
        float4 v = *(const float4*)(W2 + (size_t)n * 512 + k);
        __nv_bfloat16* r = W2s + (size_t)n * 1536 + k;
        split_store4(v, r, r + 2 * 512, r + 512);       // [hi|hi|lo]
    } else {
        const int q2 = q - Q_R2;
        const int n = q2 / 64, k = (q2 % 64) * 4;
        float4 v = make_float4(0.f, 0.f, 0.f, 0.f);
        if (n < 500) v = *(const float4*)(emb_r + (size_t)n * 256 + k);
        __nv_bfloat16* r = Ers + (size_t)n * 768 + k;
        split_store4(v, r, r + 2 * 256, r + 256);       // [hi|hi|lo]
    }
}

// ---------------- HMMA GEMM (3-stage cp.async pipeline, 1 sync/chunk) ----------------
// C[2048, 512] = A'[2048, K'] @ B'[512, K']^T   (bf16 split operands, fp32 accum)
// MODE 0: +b1, relu, split-store into g_A2 (W=512)
// MODE 1: +b2; cols<256 -> split into g_A3 (W=256); cols>=256 -> fp32 g_X2e
// MODE 2: fp32 -> g_P (stride 512)
template <int MODE>
__global__ __launch_bounds__(256, 1) void gemm_mma(
    const __nv_bfloat16* __restrict__ A, const __nv_bfloat16* __restrict__ Bm,
    int ldk, int nchunks, const float* __restrict__ bias,
    __nv_bfloat16* __restrict__ outs, float* __restrict__ outf)
{
    extern __shared__ __nv_bfloat16 sm[];
    const uint32_t smA = smem_u32(sm);                       // bytes
    const uint32_t smB = smA + NSTAGE * A_ST_EL * 2;

    const int t = threadIdx.x;
    const int warp = t >> 5, lane = t & 31;
    const int m0 = blockIdx.x * TM;
    const int n0 = blockIdx.y * TN;
    const int wm = (warp >> 2) * 32;       // 0 or 32
    const int wn = (warp & 3) * 32;        // 0..96

    // ldmatrix lane address components
    const int rA  = lane & 15;
    const int cA8 = (lane >> 4) * 8;
    const int rB  = (lane & 7) + ((lane >> 4) & 1) * 8;
    const int cB8 = ((lane >> 3) & 1) * 8;

    float acc[2][4][4] = {};

    auto load_stage = [&](int s, int chunk) {
        const size_t k0 = (size_t)chunk * TKC;
        const uint32_t dA = smA + s * A_ST_EL * 2;
        const uint32_t dB = smB + s * B_ST_EL * 2;
        #pragma unroll
        for (int i = 0; i < 2; i++) {                 // A: 512 segs
            int v = t + i * 256;
            int row = v >> 3, seg = v & 7;
            CP_ASYNC16(dA + (row * PAD_LD + seg * 8) * 2,
                       A + (size_t)(m0 + row) * ldk + k0 + seg * 8);
        }
        #pragma unroll
        for (int i = 0; i < 4; i++) {                 // B: 1024 segs
            int v = t + i * 256;
            int row = v >> 3, seg = v & 7;
            CP_ASYNC16(dB + (row * PAD_LD + seg * 8) * 2,
                       Bm + (size_t)(n0 + row) * ldk + k0 + seg * 8);
        }
        CP_COMMIT();
    };

    load_stage(0, 0);
    load_stage(1, 1);

    for (int i = 0; i < nchunks; i++) {
        if (i + 1 < nchunks) CP_WAIT(1); else CP_WAIT(0);
        __syncthreads();
        if (i + 2 < nchunks) load_stage((i + 2) % NSTAGE, i + 2);

        const uint32_t sAst = smA + (i % NSTAGE) * A_ST_EL * 2;
        const uint32_t sBst = smB + (i % NSTAGE) * B_ST_EL * 2;
        #pragma unroll
        for (int ks = 0; ks < 4; ks++) {
            const int k0 = ks * 16;
            uint32_t a0[4], a1[4], b0[4], b1[4];
            ldsm_x4(a0, sAst + ((wm +      rA) * PAD_LD + k0 + cA8) * 2);
            ldsm_x4(a1, sAst + ((wm + 16 + rA) * PAD_LD + k0 + cA8) * 2);
            ldsm_x4(b0, sBst + ((wn +      rB) * PAD_LD + k0 + cB8) * 2);
            ldsm_x4(b1, sBst + ((wn + 16 + rB) * PAD_LD + k0 + cB8) * 2);
            #pragma unroll
            for (int mi = 0; mi < 2; mi++) {
                const uint32_t* aa = mi ? a1 : a0;
                mma16816(acc[mi][0], aa, b0 + 0);
                mma16816(acc[mi][1], aa, b0 + 2);
                mma16816(acc[mi][2], aa, b1 + 0);
                mma16816(acc[mi][3], aa, b1 + 2);
            }
        }
    }

    // ---------------- epilogue ----------------
    #pragma unroll
    for (int mi = 0; mi < 2; mi++) {
        #pragma unroll
        for (int h = 0; h < 2; h++) {
            const int row = m0 + wm + 16 * mi + 8 * h + (lane >> 2);
            #pragma unroll
            for (int j = 0; j < 4; j++) {
                const int col = n0 + wn + 8 * j + 2 * (lane & 3);
                float v0 = acc[mi][j][2 * h];
                float v1 = acc[mi][j][2 * h + 1];
                if (MODE == 2) {
                    *(float2*)(outf + (size_t)row * 512 + col) = make_float2(v0, v1);
                } else {
                    v0 += __ldg(&bias[col]);
                    v1 += __ldg(&bias[col + 1]);
                    if (MODE == 0) { v0 = fmaxf(v0, 0.0f); v1 = fmaxf(v1, 0.0f); }
                    if (MODE == 1 && col >= 256) {
                        *(float2*)(outf + (size_t)row * 256 + (col - 256)) = make_float2(v0, v1);
                    } else {
                        const int W = (MODE == 0) ? 512 : 256;
                        __nv_bfloat16 h0 = __float2bfloat16_rn(v0);
                        __nv_bfloat16 h1 = __float2bfloat16_rn(v1);
                        __nv_bfloat16 l0 = __float2bfloat16_rn(v0 - __bfloat162float(h0));
                        __nv_bfloat16 l1 = __float2bfloat16_rn(v1 - __bfloat162float(h1));
                        __nv_bfloat162 hh; hh.x = h0; hh.y = h1;
                        __nv_bfloat162 ll; ll.x = l0; ll.y = l1;
                        __nv_bfloat16* r0 = outs + (size_t)row * (3 * W) + col;
                        *(__nv_bfloat162*)(r0)         = hh;
                        *(__nv_bfloat162*)(r0 + W)     = ll;
                        *(__nv_bfloat162*)(r0 + 2 * W) = hh;
                    }
                }
            }
        }
    }
}

// ---------------- score + softmax + entropy ----------------
__global__ __launch_bounds__(256) void score_softmax(
    const float* __restrict__ X2e, const float* __restrict__ P,
    const float* __restrict__ emb_e, const float* __restrict__ mask,
    const int* __restrict__ r_space, const int* __restrict__ e_space,
    float* __restrict__ out_dist, float* __restrict__ out_ent, int write_ent)
{
    const int b = blockIdx.x;
    __shared__ float x2e[256];
    __shared__ float sc[KK];
    __shared__ float red1[8], red2[8], red3[8];
    const int t = threadIdx.x;
    const int warp = t >> 5, lane = t & 31;

    x2e[t] = X2e[b * 256 + t];
    __syncthreads();

    const float4 xa = *(const float4*)&x2e[lane * 4];
    const float4 xb = *(const float4*)&x2e[lane * 4 + 128];

    for (int i = 0; i < 32; i++) {
        const int k = warp * 32 + i;
        const int e = e_space[b * KK + k];
        const float4* er = (const float4*)(emb_e + (size_t)e * 256);
        const float4 v0 = er[lane];
        const float4 v1 = er[lane + 32];
        float s = v0.x * xa.x + v0.y * xa.y + v0.z * xa.z + v0.w * xa.w
                + v1.x * xb.x + v1.y * xb.y + v1.z * xb.z + v1.w * xb.w;
#pragma unroll
        for (int o = 16; o; o >>= 1) s += __shfl_xor_sync(0xFFFFFFFFu, s, o);
        if (lane == 0) sc[k] = s;
    }
    __syncthreads();

    const int r = r_space[b * KK + t];
    float s = sc[t] + P[b * 512 + r] - (1.0f - mask[b * KK + t]) * 1e31f;

    float mx = s;
#pragma unroll
    for (int o = 16; o; o >>= 1) mx = fmaxf(mx, __shfl_xor_sync(0xFFFFFFFFu, mx, o));
    if (lane == 0) red1[warp] = mx;
    __syncthreads();
    float bm = red1[0];
#pragma unroll
    for (int w = 1; w < 8; w++) bm = fmaxf(bm, red1[w]);

    const float p = expf(s - bm);
    float sum = p;
#pragma unroll
    for (int o = 16; o; o >>= 1) sum += __shfl_xor_sync(0xFFFFFFFFu, sum, o);
    if (lane == 0) red2[warp] = sum;
    __syncthreads();
    float bs = 0.f;
#pragma unroll
    for (int w = 0; w < 8; w++) bs += red2[w];

    const float dist = p / bs;
    out_dist[b * KK + t] = dist;

    float es = -dist * logf(dist + 1e-20f);
#pragma unroll
    for (int o = 16; o; o >>= 1) es += __shfl_xor_sync(0xFFFFFFFFu, es, o);
    if (lane == 0) red3[warp] = es;
    __syncthreads();
    if (t == 0 && write_ent) {
        float tot = 0.f;
#pragma unroll
        for (int w = 0; w < 8; w++) tot += red3[w];
        out_ent[b] = tot;
    }
}

// ---------------- launcher ----------------
extern "C" void kernel_launch(void* const* d_in, const int* in_sizes, int n_in,
                              void* d_out, int out_size)
{
    const float* E     = (const float*)d_in[0];
    const float* H     = (const float*)d_in[1];
    const float* Q     = (const float*)d_in[2];
    const float* W1    = (const float*)d_in[3];
    const float* b1    = (const float*)d_in[4];
    const float* W2    = (const float*)d_in[5];
    const float* b2    = (const float*)d_in[6];
    const float* emb_r = (const float*)d_in[7];
    const float* emb_e = (const float*)d_in[8];
    const float* mask  = (const float*)d_in[9];
    const int*   r_sp  = (const int*)d_in[10];
    const int*   e_sp  = (const int*)d_in[11];
    float* out = (float*)d_out;

    __nv_bfloat16 *gA1, *gW1s, *gA2, *gW2s, *gA3, *gErs;
    float *gX2e, *gP;
    cudaGetSymbolAddress((void**)&gA1,  g_A1);
    cudaGetSymbolAddress((void**)&gW1s, g_W1s);
    cudaGetSymbolAddress((void**)&gA2,  g_A2);
    cudaGetSymbolAddress((void**)&gW2s, g_W2s);
    cudaGetSymbolAddress((void**)&gA3,  g_A3);
    cudaGetSymbolAddress((void**)&gErs, g_Ers);
    cudaGetSymbolAddress((void**)&gX2e, g_X2e);
    cudaGetSymbolAddress((void**)&gP,   g_P);

    cudaFuncSetAttribute(gemm_mma<0>, cudaFuncAttributeMaxDynamicSharedMemorySize, GEMM_SMEM);
    cudaFuncSetAttribute(gemm_mma<1>, cudaFuncAttributeMaxDynamicSharedMemorySize, GEMM_SMEM);
    cudaFuncSetAttribute(gemm_mma<2>, cudaFuncAttributeMaxDynamicSharedMemorySize, GEMM_SMEM);

    const int write_ent = (out_size >= BB * KK + BB) ? 1 : 0;

    conv_all<<<Q_TOT / 256, 256>>>(E, H, Q, W1, W2, emb_r, gA1, gW1s, gW2s, gErs);

    gemm_mma<0><<<dim3(BB / TM, 4), 256, GEMM_SMEM>>>(gA1, gW1s, 2304, 36, b1, gA2, nullptr);
    gemm_mma<1><<<dim3(BB / TM, 4), 256, GEMM_SMEM>>>(gA2, gW2s, 1536, 24, b2, gA3, gX2e);
    gemm_mma<2><<<dim3(BB / TM, 4), 256, GEMM_SMEM>>>(gA3, gErs,  768, 12, nullptr, nullptr, gP);

    score_softmax<<<BB, 256>>>(gX2e, gP, emb_e, mask, r_sp, e_sp,
                               out, out + (size_t)BB * KK, write_ent);
}

// round 5
// speedup vs baseline: 2.0311x; 1.1681x over previous
#include <cuda_runtime.h>
#include <cuda_bf16.h>
#include <math.h>
#include <stdint.h>

#define BB 2048
#define KK 256
#define AD 512
#define IN 768

// GEMM tiling: 64x64 CTA tile, 128 threads (4 warps, 32x32 each)
#define TM 64
#define TN 64
#define TKC 64                     // K-chunk (bf16 elems) = 128 B/row
#define NSTAGE 4
#define A_ST_B (TM * 128)          // 8192 B per stage
#define B_ST_B (TN * 128)          // 8192 B per stage
#define GEMM_SMEM (NSTAGE * (A_ST_B + B_ST_B))   // 65536 B

// ---------------- scratch (device globals: no allocs allowed) ----------------
__device__ __nv_bfloat16 g_A1 [(size_t)BB * 2304];   // split concat(E,H,Q)  [hi|lo|hi]
__device__ __nv_bfloat16 g_W1s[(size_t)AD * 2304];   // split W1             [hi|hi|lo]
__device__ __nv_bfloat16 g_A2 [(size_t)BB * 1536];   // split X (G1 out)
__device__ __nv_bfloat16 g_W2s[(size_t)AD * 1536];
__device__ __nv_bfloat16 g_A3 [(size_t)BB * 768];    // split X2[:, :256]
__device__ __nv_bfloat16 g_Ers[(size_t)512 * 768];   // split emb_r (rows 500..511 zero)
__device__ float g_X2e[(size_t)BB * 256];            // X2[:, 256:512] fp32
__device__ float g_P  [(size_t)BB * 512];            // X2[:, :256] @ emb_r^T

// ---------------- helpers ----------------
__device__ __forceinline__ uint32_t smem_u32(const void* p) {
    uint32_t a;
    asm("{ .reg .u64 t; cvta.to.shared.u64 t, %1; cvt.u32.u64 %0, t; }" : "=r"(a) : "l"(p));
    return a;
}
#define CP_ASYNC16(dst, src) \
    asm volatile("cp.async.cg.shared.global [%0], [%1], 16;" :: "r"(dst), "l"(src) : "memory")
#define CP_COMMIT()  asm volatile("cp.async.commit_group;" ::: "memory")
#define CP_WAIT(n)   asm volatile("cp.async.wait_group %0;" :: "n"(n) : "memory")

__device__ __forceinline__ void ldsm_x4(uint32_t* r, uint32_t addr) {
    asm volatile("ldmatrix.sync.aligned.m8n8.x4.shared.b16 {%0,%1,%2,%3}, [%4];"
                 : "=r"(r[0]), "=r"(r[1]), "=r"(r[2]), "=r"(r[3]) : "r"(addr));
}
__device__ __forceinline__ void mma16816(float* c, const uint32_t* a, const uint32_t* b) {
    asm volatile(
        "mma.sync.aligned.m16n8k16.row.col.f32.bf16.bf16.f32 "
        "{%0,%1,%2,%3}, {%4,%5,%6,%7}, {%8,%9}, {%0,%1,%2,%3};"
        : "+f"(c[0]), "+f"(c[1]), "+f"(c[2]), "+f"(c[3])
        : "r"(a[0]), "r"(a[1]), "r"(a[2]), "r"(a[3]), "r"(b[0]), "r"(b[1]));
}

// smem swizzle: 128B rows, 16B segs; seg' = seg ^ (row & 7)
__device__ __forceinline__ uint32_t swz(int row, int seg) {
    return (uint32_t)(row * 128 + ((seg ^ (row & 7)) << 4));
}

// split a float4 into hi/lo bf16 quads and store 8B each
__device__ __forceinline__ void split_store4(float4 v, __nv_bfloat16* d_hi,
                                             __nv_bfloat16* d_lo, __nv_bfloat16* d_hi2)
{
    __align__(8) __nv_bfloat16 hh[4], ll[4];
    hh[0] = __float2bfloat16_rn(v.x); ll[0] = __float2bfloat16_rn(v.x - __bfloat162float(hh[0]));
    hh[1] = __float2bfloat16_rn(v.y); ll[1] = __float2bfloat16_rn(v.y - __bfloat162float(hh[1]));
    hh[2] = __float2bfloat16_rn(v.z); ll[2] = __float2bfloat16_rn(v.z - __bfloat162float(hh[2]));
    hh[3] = __float2bfloat16_rn(v.w); ll[3] = __float2bfloat16_rn(v.w - __bfloat162float(hh[3]));
    *(uint2*)d_hi  = *(uint2*)hh;
    *(uint2*)d_lo  = *(uint2*)ll;
    *(uint2*)d_hi2 = *(uint2*)hh;
}

// ---------------- fused conversion kernel ----------------
#define Q_R0 (BB * IN / 4)               // 393216
#define Q_R1 (Q_R0 + 512 * 768 / 4)      // 491520
#define Q_R2 (Q_R1 + 512 * 512 / 4)      // 557056
#define Q_TOT (Q_R2 + 512 * 256 / 4)     // 589824

__global__ __launch_bounds__(256) void conv_all(
    const float* __restrict__ E, const float* __restrict__ H, const float* __restrict__ Qm,
    const float* __restrict__ W1, const float* __restrict__ W2, const float* __restrict__ emb_r,
    __nv_bfloat16* __restrict__ A1, __nv_bfloat16* __restrict__ W1s,
    __nv_bfloat16* __restrict__ W2s, __nv_bfloat16* __restrict__ Ers)
{
    const int q = blockIdx.x * 256 + threadIdx.x;
    if (q < Q_R0) {
        const int m = q / 192, c = (q % 192) * 4;
        const float* src = (c < 256) ? (E + m * 256 + c)
                         : (c < 512) ? (H + m * 256 + (c - 256))
                                     : (Qm + m * 256 + (c - 512));
        float4 v = *(const float4*)src;
        __nv_bfloat16* r = A1 + (size_t)m * 2304 + c;
        split_store4(v, r, r + 768, r + 1536);          // [hi|lo|hi]
    } else if (q < Q_R1) {
        const int q2 = q - Q_R0;
        const int n = q2 / 192, k = (q2 % 192) * 4;
        float4 v = *(const float4*)(W1 + (size_t)n * 768 + k);
        __nv_bfloat16* r = W1s + (size_t)n * 2304 + k;
        split_store4(v, r, r + 2 * 768, r + 768);       // [hi|hi|lo]
    } else if (q < Q_R2) {
        const int q2 = q - Q_R1;
        const int n = q2 / 128, k = (q2 % 128) * 4;
        float4 v = *(const float4*)(W2 + (size_t)n * 512 + k);
        __nv_bfloat16* r = W2s + (size_t)n * 1536 + k;
        split_store4(v, r, r + 2 * 512, r + 512);       // [hi|hi|lo]
    } else {
        const int q2 = q - Q_R2;
        const int n = q2 / 64, k = (q2 % 64) * 4;
        float4 v = make_float4(0.f, 0.f, 0.f, 0.f);
        if (n < 500) v = *(const float4*)(emb_r + (size_t)n * 256 + k);
        __nv_bfloat16* r = Ers + (size_t)n * 768 + k;
        split_store4(v, r, r + 2 * 256, r + 256);       // [hi|hi|lo]
    }
}

// ---------------- HMMA GEMM (64x64 tiles, 4-stage pipeline, swizzled smem) ----------------
// MODE 0: +b1, relu, split-store into g_A2 (W=512)
// MODE 1: +b2; cols<256 -> split into g_A3 (W=256); cols>=256 -> fp32 g_X2e
// MODE 2: fp32 -> g_P (stride 512)
template <int MODE>
__global__ __launch_bounds__(128) void gemm_mma(
    const __nv_bfloat16* __restrict__ A, const __nv_bfloat16* __restrict__ Bm,
    int ldk, int nchunks, const float* __restrict__ bias,
    __nv_bfloat16* __restrict__ outs, float* __restrict__ outf)
{
    extern __shared__ __nv_bfloat16 sm[];
    const uint32_t smA = smem_u32(sm);
    const uint32_t smB = smA + NSTAGE * A_ST_B;

    const int t = threadIdx.x;
    const int warp = t >> 5, lane = t & 31;
    const int m0 = blockIdx.x * TM;
    const int n0 = blockIdx.y * TN;
    const int wm = (warp >> 1) * 32;       // 0 or 32
    const int wn = (warp & 1) * 32;        // 0 or 32

    // ldmatrix lane row/seg components
    const int rA  = lane & 15;
    const int sA8 = (lane >> 4);                  // +0/+1 seg (8 elems)
    const int rB  = (lane & 7) + ((lane >> 4) & 1) * 8;
    const int sB8 = ((lane >> 3) & 1);

    float acc[2][4][4] = {};

    auto load_stage = [&](int s, int chunk) {
        const size_t k0 = (size_t)chunk * TKC;
        const uint32_t dA = smA + s * A_ST_B;
        const uint32_t dB = smB + s * B_ST_B;
        #pragma unroll
        for (int i = 0; i < 4; i++) {                 // A: 512 segs, 4/thread
            int v = t + i * 128;
            int row = v >> 3, seg = v & 7;
            CP_ASYNC16(dA + swz(row, seg),
                       A + (size_t)(m0 + row) * ldk + k0 + seg * 8);
        }
        #pragma unroll
        for (int i = 0; i < 4; i++) {                 // B: 512 segs, 4/thread
            int v = t + i * 128;
            int row = v >> 3, seg = v & 7;
            CP_ASYNC16(dB + swz(row, seg),
                       Bm + (size_t)(n0 + row) * ldk + k0 + seg * 8);
        }
        CP_COMMIT();
    };

    load_stage(0, 0);
    load_stage(1, 1);
    load_stage(2, 2);

    for (int i = 0; i < nchunks; i++) {
        CP_WAIT(2);
        __syncthreads();
        if (i + 3 < nchunks) load_stage((i + 3) % NSTAGE, i + 3);
        else CP_COMMIT();                                   // keep pending-count invariant

        const uint32_t sAst = smA + (i % NSTAGE) * A_ST_B;
        const uint32_t sBst = smB + (i % NSTAGE) * B_ST_B;
        #pragma unroll
        for (int ks = 0; ks < 4; ks++) {
            uint32_t a0[4], a1[4], b0[4], b1[4];
            const int segK = ks * 2;
            {
                const int r0 = wm + rA,  r1 = wm + 16 + rA;
                ldsm_x4(a0, sAst + swz(r0, segK + sA8));
                ldsm_x4(a1, sAst + swz(r1, segK + sA8));
            }
            {
                const int r0 = wn + rB,  r1 = wn + 16 + rB;
                ldsm_x4(b0, sBst + swz(r0, segK + sB8));
                ldsm_x4(b1, sBst + swz(r1, segK + sB8));
            }
            #pragma unroll
            for (int mi = 0; mi < 2; mi++) {
                const uint32_t* aa = mi ? a1 : a0;
                mma16816(acc[mi][0], aa, b0 + 0);
                mma16816(acc[mi][1], aa, b0 + 2);
                mma16816(acc[mi][2], aa, b1 + 0);
                mma16816(acc[mi][3], aa, b1 + 2);
            }
        }
    }

    // ---------------- epilogue ----------------
    #pragma unroll
    for (int mi = 0; mi < 2; mi++) {
        #pragma unroll
        for (int h = 0; h < 2; h++) {
            const int row = m0 + wm + 16 * mi + 8 * h + (lane >> 2);
            #pragma unroll
            for (int j = 0; j < 4; j++) {
                const int col = n0 + wn + 8 * j + 2 * (lane & 3);
                float v0 = acc[mi][j][2 * h];
                float v1 = acc[mi][j][2 * h + 1];
                if (MODE == 2) {
                    *(float2*)(outf + (size_t)row * 512 + col) = make_float2(v0, v1);
                } else {
                    v0 += __ldg(&bias[col]);
                    v1 += __ldg(&bias[col + 1]);
                    if (MODE == 0) { v0 = fmaxf(v0, 0.0f); v1 = fmaxf(v1, 0.0f); }
                    if (MODE == 1 && col >= 256) {
                        *(float2*)(outf + (size_t)row * 256 + (col - 256)) = make_float2(v0, v1);
                    } else {
                        const int W = (MODE == 0) ? 512 : 256;
                        __nv_bfloat16 h0 = __float2bfloat16_rn(v0);
                        __nv_bfloat16 h1 = __float2bfloat16_rn(v1);
                        __nv_bfloat16 l0 = __float2bfloat16_rn(v0 - __bfloat162float(h0));
                        __nv_bfloat16 l1 = __float2bfloat16_rn(v1 - __bfloat162float(h1));
                        __nv_bfloat162 hh; hh.x = h0; hh.y = h1;
                        __nv_bfloat162 ll; ll.x = l0; ll.y = l1;
                        __nv_bfloat16* r0 = outs + (size_t)row * (3 * W) + col;
                        *(__nv_bfloat162*)(r0)         = hh;
                        *(__nv_bfloat162*)(r0 + W)     = ll;
                        *(__nv_bfloat162*)(r0 + 2 * W) = hh;
                    }
                }
            }
        }
    }
}

// ---------------- score + softmax + entropy ----------------
__global__ __launch_bounds__(256) void score_softmax(
    const float* __restrict__ X2e, const float* __restrict__ P,
    const float* __restrict__ emb_e, const float* __restrict__ mask,
    const int* __restrict__ r_space, const int* __restrict__ e_space,
    float* __restrict__ out_dist, float* __restrict__ out_ent, int write_ent)
{
    const int b = blockIdx.x;
    __shared__ float x2e[256];
    __shared__ float sc[KK];
    __shared__ float red1[8], red2[8], red3[8];
    const int t = threadIdx.x;
    const int warp = t >> 5, lane = t & 31;

    x2e[t] = X2e[b * 256 + t];
    __syncthreads();

    const float4 xa = *(const float4*)&x2e[lane * 4];
    const float4 xb = *(const float4*)&x2e[lane * 4 + 128];

    for (int i = 0; i < 32; i++) {
        const int k = warp * 32 + i;
        const int e = e_space[b * KK + k];
        const float4* er = (const float4*)(emb_e + (size_t)e * 256);
        const float4 v0 = er[lane];
        const float4 v1 = er[lane + 32];
        float s = v0.x * xa.x + v0.y * xa.y + v0.z * xa.z + v0.w * xa.w
                + v1.x * xb.x + v1.y * xb.y + v1.z * xb.z + v1.w * xb.w;
#pragma unroll
        for (int o = 16; o; o >>= 1) s += __shfl_xor_sync(0xFFFFFFFFu, s, o);
        if (lane == 0) sc[k] = s;
    }
    __syncthreads();

    const int r = r_space[b * KK + t];
    float s = sc[t] + P[b * 512 + r] - (1.0f - mask[b * KK + t]) * 1e31f;

    float mx = s;
#pragma unroll
    for (int o = 16; o; o >>= 1) mx = fmaxf(mx, __shfl_xor_sync(0xFFFFFFFFu, mx, o));
    if (lane == 0) red1[warp] = mx;
    __syncthreads();
    float bm = red1[0];
#pragma unroll
    for (int w = 1; w < 8; w++) bm = fmaxf(bm, red1[w]);

    const float p = expf(s - bm);
    float sum = p;
#pragma unroll
    for (int o = 16; o; o >>= 1) sum += __shfl_xor_sync(0xFFFFFFFFu, sum, o);
    if (lane == 0) red2[warp] = sum;
    __syncthreads();
    float bs = 0.f;
#pragma unroll
    for (int w = 0; w < 8; w++) bs += red2[w];

    const float dist = p / bs;
    out_dist[b * KK + t] = dist;

    float es = -dist * logf(dist + 1e-20f);
#pragma unroll
    for (int o = 16; o; o >>= 1) es += __shfl_xor_sync(0xFFFFFFFFu, es, o);
    if (lane == 0) red3[warp] = es;
    __syncthreads();
    if (t == 0 && write_ent) {
        float tot = 0.f;
#pragma unroll
        for (int w = 0; w < 8; w++) tot += red3[w];
        out_ent[b] = tot;
    }
}

// ---------------- launcher ----------------
extern "C" void kernel_launch(void* const* d_in, const int* in_sizes, int n_in,
                              void* d_out, int out_size)
{
    const float* E     = (const float*)d_in[0];
    const float* H     = (const float*)d_in[1];
    const float* Q     = (const float*)d_in[2];
    const float* W1    = (const float*)d_in[3];
    const float* b1    = (const float*)d_in[4];
    const float* W2    = (const float*)d_in[5];
    const float* b2    = (const float*)d_in[6];
    const float* emb_r = (const float*)d_in[7];
    const float* emb_e = (const float*)d_in[8];
    const float* mask  = (const float*)d_in[9];
    const int*   r_sp  = (const int*)d_in[10];
    const int*   e_sp  = (const int*)d_in[11];
    float* out = (float*)d_out;

    __nv_bfloat16 *gA1, *gW1s, *gA2, *gW2s, *gA3, *gErs;
    float *gX2e, *gP;
    cudaGetSymbolAddress((void**)&gA1,  g_A1);
    cudaGetSymbolAddress((void**)&gW1s, g_W1s);
    cudaGetSymbolAddress((void**)&gA2,  g_A2);
    cudaGetSymbolAddress((void**)&gW2s, g_W2s);
    cudaGetSymbolAddress((void**)&gA3,  g_A3);
    cudaGetSymbolAddress((void**)&gErs, g_Ers);
    cudaGetSymbolAddress((void**)&gX2e, g_X2e);
    cudaGetSymbolAddress((void**)&gP,   g_P);

    cudaFuncSetAttribute(gemm_mma<0>, cudaFuncAttributeMaxDynamicSharedMemorySize, GEMM_SMEM);
    cudaFuncSetAttribute(gemm_mma<1>, cudaFuncAttributeMaxDynamicSharedMemorySize, GEMM_SMEM);
    cudaFuncSetAttribute(gemm_mma<2>, cudaFuncAttributeMaxDynamicSharedMemorySize, GEMM_SMEM);

    const int write_ent = (out_size >= BB * KK + BB) ? 1 : 0;

    conv_all<<<Q_TOT / 256, 256>>>(E, H, Q, W1, W2, emb_r, gA1, gW1s, gW2s, gErs);

    gemm_mma<0><<<dim3(BB / TM, AD / TN), 128, GEMM_SMEM>>>(gA1, gW1s, 2304, 36, b1, gA2, nullptr);
    gemm_mma<1><<<dim3(BB / TM, AD / TN), 128, GEMM_SMEM>>>(gA2, gW2s, 1536, 24, b2, gA3, gX2e);
    gemm_mma<2><<<dim3(BB / TM, AD / TN), 128, GEMM_SMEM>>>(gA3, gErs,  768, 12, nullptr, nullptr, gP);

    score_softmax<<<BB, 256>>>(gX2e, gP, emb_e, mask, r_sp, e_sp,
                               out, out + (size_t)BB * KK, write_ent);
}